// round 10
// baseline (speedup 1.0000x reference)
#include <cuda_runtime.h>

#define NB      32
#define NIN     1034
#define NOUT    512
#define STRIDE  1152       // padded: reads up to pk[k0+64] with k0<=1024
#define KNS     1000.0f
#define MINW    (-0.3678794411714423f)
#define EF      2.718281828459045f
#define NBUCK   2048

// packed per-batch sorted data: (t, e^t, t*e^t, idx-as-int-bits)
__device__ float4 g_pack[NB * STRIDE];

__device__ __forceinline__ float get_t(const float* __restrict__ x,
                                       const float* __restrict__ pulse,
                                       int b, int i) {
    return (i < 1024) ? x[b * 1024 + i] : pulse[i - 1024];
}

__device__ __forceinline__ int bucket_of(float t) {
    int bid = (int)(t * (float)NBUCK);
    return bid < 0 ? 0 : (bid >= NBUCK ? NBUCK - 1 : bid);
}

// ---------------------------------------------------------------------------
// Kernel 1: per-batch bucket sort + pack.  grid=NB, block=1024.
// ---------------------------------------------------------------------------
__global__ void sort_pack_kernel(const float* __restrict__ x,
                                 const float* __restrict__ pulse) {
    __shared__ int cnt [NBUCK];
    __shared__ int base[NBUCK];
    __shared__ unsigned long long keys[NIN];
    __shared__ float wsum[32];

    const int b   = blockIdx.x;
    const int tid = threadIdx.x;
    const int lane = tid & 31, wid = tid >> 5;

    cnt[tid] = 0; cnt[tid + 1024] = 0;
    __syncthreads();

    for (int i = tid; i < NIN; i += 1024) {
        const float t = get_t(x, pulse, b, i);
        atomicAdd(&cnt[bucket_of(t)], 1);
    }
    __syncthreads();

    {
        const int v0 = cnt[2 * tid], v1 = cnt[2 * tid + 1];
        float s = (float)(v0 + v1);
        #pragma unroll
        for (int off = 1; off < 32; off <<= 1) {
            const float u = __shfl_up_sync(0xffffffffu, s, off);
            if (lane >= off) s += u;
        }
        if (lane == 31) wsum[wid] = s;
        __syncthreads();
        if (wid == 0) {
            float ws = wsum[lane];
            #pragma unroll
            for (int off = 1; off < 32; off <<= 1) {
                const float u = __shfl_up_sync(0xffffffffu, ws, off);
                if (lane >= off) ws += u;
            }
            wsum[lane] = ws;
        }
        __syncthreads();
        const int incl = (int)s + (wid ? (int)wsum[wid - 1] : 0);
        const int excl = incl - v0 - v1;
        base[2 * tid]     = excl;
        base[2 * tid + 1] = excl + v0;
        __syncthreads();
        cnt[2 * tid]     = excl;
        cnt[2 * tid + 1] = excl + v0;
    }
    __syncthreads();

    for (int i = tid; i < NIN; i += 1024) {
        const float t = get_t(x, pulse, b, i);
        const int pos = atomicAdd(&cnt[bucket_of(t)], 1);
        keys[pos] = ((unsigned long long)__float_as_uint(t) << 32) | (unsigned)i;
    }
    __syncthreads();

    for (int bk = tid; bk < NBUCK; bk += 1024) {
        const int s0 = base[bk];
        const int s1 = (bk + 1 < NBUCK) ? base[bk + 1] : NIN;
        for (int i = s0 + 1; i < s1; ++i) {
            const unsigned long long v = keys[i];
            int j = i - 1;
            while (j >= s0 && keys[j] > v) { keys[j + 1] = keys[j]; --j; }
            keys[j + 1] = v;
        }
    }
    __syncthreads();

    for (int i = tid; i < STRIDE; i += 1024) {
        if (i < NIN) {
            const unsigned long long v = keys[i];
            const float t = __uint_as_float((unsigned)(v >> 32));
            const int idx = (int)(unsigned)v;
            const float z = expf(t);
            g_pack[b * STRIDE + i] = make_float4(t, z, z * t, __int_as_float(idx));
        } else {
            g_pack[b * STRIDE + i] = make_float4(KNS, 0.0f, 0.0f, 0.0f);
        }
    }
}

// packed f32x2 helpers (Blackwell)
__device__ __forceinline__ unsigned long long pack2(float lo, float hi) {
    unsigned long long r;
    asm("mov.b64 %0, {%1, %2};" : "=l"(r) : "f"(lo), "f"(hi));
    return r;
}
__device__ __forceinline__ void unpack2(unsigned long long v, float& lo, float& hi) {
    asm("mov.b64 {%0, %1}, %2;" : "=f"(lo), "=f"(hi) : "l"(v));
}
__device__ __forceinline__ unsigned long long addf32x2(unsigned long long a,
                                                       unsigned long long b) {
    unsigned long long r;
    asm("add.rn.f32x2 %0, %1, %2;" : "=l"(r) : "l"(a), "l"(b));
    return r;
}

// ---------------------------------------------------------------------------
// Kernel 2: one warp per (batch, output). Each lane holds 2 adjacent sorted
// elements -> one work-efficient packed scan covers 64 inputs per pass.
// Analytic window tests (div-free); one deferred Lambert solve per pair.
// ---------------------------------------------------------------------------
__global__ void __launch_bounds__(128)
solve_kernel(const float* __restrict__ W, float* __restrict__ out) {
    const int gw   = (int)((blockIdx.x * blockDim.x + threadIdx.x) >> 5);
    const int lane = threadIdx.x & 31;
    const int b    = gw >> 9;
    const int o    = gw & 511;

    const float4* __restrict__ pk   = g_pack + b * STRIDE;
    const float*  __restrict__ wrow = W + o * NIN;

    unsigned long long carry = pack2(0.0f, 0.0f);
    unsigned long long winAB = 0ull;
    bool spiked = false;

    for (int k0 = 0; k0 < NIN && !spiked; k0 += 64) {
        const int k = k0 + 2 * lane;
        const float4 p0 = pk[k];
        const float4 p1 = pk[k + 1];
        const float t0 = p0.x, z0 = p0.y;
        const float t1 = p1.x, z1 = p1.y;
        const float w0 = wrow[__float_as_int(p0.w)];
        const float w1 = wrow[__float_as_int(p1.w)];

        // per-lane pair values (A,B contributions), packed
        const unsigned long long v0  = pack2(w0 * z0, w0 * p0.z);
        const unsigned long long v01 = addf32x2(v0, pack2(w1 * z1, w1 * p1.z));

        // inclusive scan of pair-sums across lanes
        unsigned long long s = v01;
        #pragma unroll
        for (int off = 1; off < 32; off <<= 1) {
            const unsigned long long u = __shfl_up_sync(0xffffffffu, s, off);
            if (lane >= off) s = addf32x2(s, u);
        }
        // exclusive shift
        unsigned long long ex = __shfl_up_sync(0xffffffffu, s, 1);
        if (lane == 0) ex = 0ull;

        const unsigned long long cum0 = addf32x2(carry, addf32x2(ex, v0));
        const unsigned long long cum1 = addf32x2(carry, s);

        // next (t,z) for element 1's upper test = next lane's element 0
        unsigned long long ntz = __shfl_down_sync(0xffffffffu, pack2(t0, z0), 1);
        float nt1, nz1;
        unpack2(ntz, nt1, nz1);
        if (lane == 31) { const float4 q = pk[k0 + 64]; nt1 = q.x; nz1 = q.y; }

        float A0, B0, A1, B1;
        unpack2(cum0, A0, B0);
        unpack2(cum1, A1, B1);

        // div-free window tests:
        //  reach: A(lnA - 1) >= B      (arg >= -1/e)
        //  lower: A*t_k - B <= z_k     (t* >= t_k)
        //  upper: t_{k+1} >= lnA  ||  A*t_{k+1} - B >= z_{k+1}
        bool valid0 = false, valid1 = false;
        if (A0 > 1e-10f) {
            const float lnA = __logf(A0);
            valid0 = (fmaf(A0, lnA - 1.0f, -B0) >= 0.0f)
                  && (fmaf(A0, t0, -B0) <= z0)
                  && ((t1 >= lnA) || (fmaf(A0, t1, -B0) >= z1))
                  && (t0 < KNS);
        }
        if (A1 > 1e-10f) {
            const float lnA = __logf(A1);
            valid1 = (fmaf(A1, lnA - 1.0f, -B1) >= 0.0f)
                  && (fmaf(A1, t1, -B1) <= z1)
                  && ((nt1 >= lnA) || (fmaf(A1, nt1, -B1) >= nz1))
                  && (t1 < KNS);
        }

        const unsigned m0 = __ballot_sync(0xffffffffu, valid0);
        const unsigned m1 = __ballot_sync(0xffffffffu, valid1);
        if (m0 | m1) {
            const int p0v = m0 ? ((__ffs((int)m0) - 1) << 1)       : (1 << 30);
            const int p1v = m1 ? (((__ffs((int)m1) - 1) << 1) | 1) : (1 << 30);
            const int wp  = min(p0v, p1v);          // first valid in k-order
            const unsigned long long chosen = (wp & 1) ? cum1 : cum0;
            winAB = __shfl_sync(0xffffffffu, chosen, wp >> 1);
            spiked = true;
        } else {
            carry = addf32x2(carry, __shfl_sync(0xffffffffu, s, 31));
        }
    }

    // one deferred Lambert solve per (b,o)
    if (lane == 0) {
        float tc = KNS;
        if (spiked) {
            float A, B;
            unpack2(winAB, A, B);
            const float boa = B / A;
            float xw = -1.0f / A * expf(fminf(boa, 80.0f));
            xw = fmaxf(fminf(xw, 0.0f), MINW);
            float wv;
            if (xw < -0.25f) {
                const float pbr = sqrtf(fmaxf(2.0f * (1.0f + EF * xw), 0.0f));
                wv = -1.0f + pbr * (1.0f + pbr * (-0.33333333f + pbr * 0.15277778f));
            } else {
                wv = xw * (1.0f - xw * (1.0f - 1.5f * xw));
            }
            #pragma unroll
            for (int it = 0; it < 3; ++it) {
                const float ew = expf(wv);
                const float f  = wv * ew - xw;
                const float denom = ew * (wv + 1.0f)
                          - (wv + 2.0f) * f / (2.0f * (wv + 1.0f) + 1e-12f);
                wv = wv - f / (denom + 1e-12f);
            }
            tc = boa - wv;
        }
        out[b * NOUT + o] = tc;
    }
}

// ---------------------------------------------------------------------------
extern "C" void kernel_launch(void* const* d_in, const int* in_sizes, int n_in,
                              void* d_out, int out_size) {
    const float* x      = (const float*)d_in[0];   // [32, 1024]
    const float* weight = (const float*)d_in[1];   // [512, 1034]
    const float* pulse  = (const float*)d_in[2];   // [10]
    float* out = (float*)d_out;                    // [32, 512]

    sort_pack_kernel<<<NB, 1024>>>(x, pulse);

    // one warp per (b,o): 16384 warps, 128-thr blocks -> 4096 blocks
    const int warps = NB * NOUT;
    solve_kernel<<<warps / 4, 128>>>(weight, out);
}

// round 11
// speedup vs baseline: 1.1808x; 1.1808x over previous
#include <cuda_runtime.h>

#define NB      32
#define NIN     1034
#define NOUT    512
#define STRIDE  1088
#define KNS     1000.0f
#define MINW    (-0.3678794411714423f)
#define EF      2.718281828459045f
#define NBUCK   2048
#define GROUP   16

// packed per-batch sorted data: (t, e^t, t*e^t, idx-as-int-bits)
__device__ float4 g_pack[NB * STRIDE];
// transposed weights: Wt[i][o], 1034 x 512
__device__ float  g_wt[NIN * NOUT];

__device__ __forceinline__ float get_t(const float* __restrict__ x,
                                       const float* __restrict__ pulse,
                                       int b, int i) {
    return (i < 1024) ? x[b * 1024 + i] : pulse[i - 1024];
}

__device__ __forceinline__ int bucket_of(float t) {
    int bid = (int)(t * (float)NBUCK);
    return bid < 0 ? 0 : (bid >= NBUCK ? NBUCK - 1 : bid);
}

// ---------------------------------------------------------------------------
// Kernel 1: per-batch bucket sort + pack.  grid=NB, block=1024.
// ---------------------------------------------------------------------------
__global__ void sort_pack_kernel(const float* __restrict__ x,
                                 const float* __restrict__ pulse) {
    __shared__ int cnt [NBUCK];
    __shared__ int base[NBUCK];
    __shared__ unsigned long long keys[NIN];
    __shared__ float wsum[32];

    const int b   = blockIdx.x;
    const int tid = threadIdx.x;
    const int lane = tid & 31, wid = tid >> 5;

    cnt[tid] = 0; cnt[tid + 1024] = 0;
    __syncthreads();

    for (int i = tid; i < NIN; i += 1024) {
        const float t = get_t(x, pulse, b, i);
        atomicAdd(&cnt[bucket_of(t)], 1);
    }
    __syncthreads();

    {
        const int v0 = cnt[2 * tid], v1 = cnt[2 * tid + 1];
        float s = (float)(v0 + v1);
        #pragma unroll
        for (int off = 1; off < 32; off <<= 1) {
            const float u = __shfl_up_sync(0xffffffffu, s, off);
            if (lane >= off) s += u;
        }
        if (lane == 31) wsum[wid] = s;
        __syncthreads();
        if (wid == 0) {
            float ws = wsum[lane];
            #pragma unroll
            for (int off = 1; off < 32; off <<= 1) {
                const float u = __shfl_up_sync(0xffffffffu, ws, off);
                if (lane >= off) ws += u;
            }
            wsum[lane] = ws;
        }
        __syncthreads();
        const int incl = (int)s + (wid ? (int)wsum[wid - 1] : 0);
        const int excl = incl - v0 - v1;
        base[2 * tid]     = excl;
        base[2 * tid + 1] = excl + v0;
        __syncthreads();
        cnt[2 * tid]     = excl;
        cnt[2 * tid + 1] = excl + v0;
    }
    __syncthreads();

    for (int i = tid; i < NIN; i += 1024) {
        const float t = get_t(x, pulse, b, i);
        const int pos = atomicAdd(&cnt[bucket_of(t)], 1);
        keys[pos] = ((unsigned long long)__float_as_uint(t) << 32) | (unsigned)i;
    }
    __syncthreads();

    for (int bk = tid; bk < NBUCK; bk += 1024) {
        const int s0 = base[bk];
        const int s1 = (bk + 1 < NBUCK) ? base[bk + 1] : NIN;
        for (int i = s0 + 1; i < s1; ++i) {
            const unsigned long long v = keys[i];
            int j = i - 1;
            while (j >= s0 && keys[j] > v) { keys[j + 1] = keys[j]; --j; }
            keys[j + 1] = v;
        }
    }
    __syncthreads();

    for (int i = tid; i < STRIDE; i += 1024) {
        if (i < NIN) {
            const unsigned long long v = keys[i];
            const float t = __uint_as_float((unsigned)(v >> 32));
            const int idx = (int)(unsigned)v;
            const float z = expf(t);
            g_pack[b * STRIDE + i] = make_float4(t, z, z * t, __int_as_float(idx));
        } else {
            g_pack[b * STRIDE + i] = make_float4(KNS, 0.0f, 0.0f, 0.0f);
        }
    }
}

// ---------------------------------------------------------------------------
// Kernel 2: tiled transpose W[512][1034] -> g_wt[1034][512]
// ---------------------------------------------------------------------------
__global__ void transpose_kernel(const float* __restrict__ W) {
    __shared__ float tile[32][33];
    const int i0 = blockIdx.x * 32;   // input-feature tile base
    const int o0 = blockIdx.y * 32;   // output tile base
    const int x = threadIdx.x, y = threadIdx.y;   // 32 x 8

    #pragma unroll
    for (int dy = 0; dy < 32; dy += 8) {
        const int o = o0 + y + dy, i = i0 + x;
        if (i < NIN) tile[y + dy][x] = W[o * NIN + i];
    }
    __syncthreads();
    #pragma unroll
    for (int dy = 0; dy < 32; dy += 8) {
        const int i = i0 + y + dy, o = o0 + x;
        if (i < NIN) g_wt[i * NOUT + o] = tile[x][y + dy];
    }
}

// ---------------------------------------------------------------------------
// Kernel 3: one THREAD per (batch, output). Serial causal-set scan with
// coalesced transposed-weight reads; div-free window tests; first-valid
// latch; one Lambert solve per thread at the end.
// ---------------------------------------------------------------------------
__global__ void solve_kernel(float* __restrict__ out) {
    const int gt = blockIdx.x * blockDim.x + threadIdx.x;
    const int b  = gt >> 9;          // / 512  (block of 128: all same b)
    const int o  = gt & 511;

    const float4* __restrict__ pk = g_pack + b * STRIDE;
    const float*  __restrict__ wt = g_wt;

    float A = 0.0f, Bv = 0.0f;
    float fA = 1.0f, fB = 0.0f;
    bool  found = false;

    for (int k0 = 0; k0 < NIN; k0 += GROUP) {
        // batch-load GROUP pk entries (warp-uniform broadcast) + lookahead
        float4 p[GROUP];
        #pragma unroll
        for (int j = 0; j < GROUP; ++j) p[j] = pk[k0 + j];
        const float4 q = pk[k0 + GROUP];           // next-group head (lookahead)

        // batch-gather GROUP weights: Wt[idx*512 + o] — 1 coalesced line/warp
        float w[GROUP];
        #pragma unroll
        for (int j = 0; j < GROUP; ++j)
            w[j] = wt[__float_as_int(p[j].w) * NOUT + o];

        // serial causal-set accumulate + first-valid latch
        #pragma unroll
        for (int j = 0; j < GROUP; ++j) {
            A  = fmaf(w[j], p[j].y, A);
            Bv = fmaf(w[j], p[j].z, Bv);
            if (!found && A > 1e-10f) {
                const float lnA = __logf(A);
                const float tn  = (j < GROUP - 1) ? p[j + 1].x : q.x;
                const float zn  = (j < GROUP - 1) ? p[j + 1].y : q.y;
                // reach: A(lnA-1) >= B;  lower: A t_k - B <= z_k;
                // upper: t_{k+1} >= lnA  ||  A t_{k+1} - B >= z_{k+1}
                const bool valid =
                       (fmaf(A, lnA - 1.0f, -Bv) >= 0.0f)
                    && (fmaf(A, p[j].x, -Bv) <= p[j].y)
                    && ((tn >= lnA) || (fmaf(A, tn, -Bv) >= zn))
                    && (p[j].x < KNS);
                if (valid) { found = true; fA = A; fB = Bv; }
            }
        }
        if (__all_sync(0xffffffffu, found)) break;
    }

    // one Lambert solve per thread
    float tc = KNS;
    if (found) {
        const float boa = fB / fA;
        float xw = -1.0f / fA * expf(fminf(boa, 80.0f));
        xw = fmaxf(fminf(xw, 0.0f), MINW);
        float wv;
        if (xw < -0.25f) {
            const float pbr = sqrtf(fmaxf(2.0f * (1.0f + EF * xw), 0.0f));
            wv = -1.0f + pbr * (1.0f + pbr * (-0.33333333f + pbr * 0.15277778f));
        } else {
            wv = xw * (1.0f - xw * (1.0f - 1.5f * xw));
        }
        #pragma unroll
        for (int it = 0; it < 3; ++it) {
            const float ew = expf(wv);
            const float f  = wv * ew - xw;
            const float denom = ew * (wv + 1.0f)
                      - (wv + 2.0f) * f / (2.0f * (wv + 1.0f) + 1e-12f);
            wv = wv - f / (denom + 1e-12f);
        }
        tc = boa - wv;
    }
    out[b * NOUT + o] = tc;
}

// ---------------------------------------------------------------------------
extern "C" void kernel_launch(void* const* d_in, const int* in_sizes, int n_in,
                              void* d_out, int out_size) {
    const float* x      = (const float*)d_in[0];   // [32, 1024]
    const float* weight = (const float*)d_in[1];   // [512, 1034]
    const float* pulse  = (const float*)d_in[2];   // [10]
    float* out = (float*)d_out;                    // [32, 512]

    sort_pack_kernel<<<NB, 1024>>>(x, pulse);
    transpose_kernel<<<dim3((NIN + 31) / 32, NOUT / 32), dim3(32, 8)>>>(weight);

    // one thread per (b,o): 16384 threads, 128-thr blocks
    solve_kernel<<<(NB * NOUT) / 128, 128>>>(out);
}

// round 12
// speedup vs baseline: 1.2982x; 1.0994x over previous
#include <cuda_runtime.h>

#define NB      32
#define NIN     1034
#define NOUT    512
#define STRIDE  1088
#define KNS     1000.0f
#define MINW    (-0.3678794411714423f)
#define EF      2.718281828459045f
#define NBUCK   2048
#define GROUP   8
#define ITILES  33          // ceil(1034/32)
#define OTILES  16          // 512/32

// packed per-batch sorted data: (t, e^t, t*e^t, idx-as-int-bits)
__device__ float4 g_pack[NB * STRIDE];
// transposed weights: Wt[i][o], 1034 x 512
__device__ float  g_wt[NIN * NOUT];

__device__ __forceinline__ float get_t(const float* __restrict__ x,
                                       const float* __restrict__ pulse,
                                       int b, int i) {
    return (i < 1024) ? x[b * 1024 + i] : pulse[i - 1024];
}

__device__ __forceinline__ int bucket_of(float t) {
    int bid = (int)(t * (float)NBUCK);
    return bid < 0 ? 0 : (bid >= NBUCK ? NBUCK - 1 : bid);
}

// ---------------------------------------------------------------------------
// Kernel 1 (fused): blocks 0..31 -> per-batch bucket sort + pack;
//                   blocks 32..559 -> 32x32 transpose tiles of W.
// 1024 threads per block.
// ---------------------------------------------------------------------------
__global__ void prep_kernel(const float* __restrict__ x,
                            const float* __restrict__ pulse,
                            const float* __restrict__ W) {
    __shared__ int cnt [NBUCK];
    __shared__ int base[NBUCK];
    __shared__ unsigned long long keys[NIN];
    __shared__ float wsum[32];
    __shared__ float tile[32][33];

    const int bid = blockIdx.x;
    const int tid = threadIdx.x;

    if (bid >= NB) {
        // ----- transpose path -----
        const int tb = bid - NB;
        const int i0 = (tb % ITILES) * 32;
        const int o0 = (tb / ITILES) * 32;
        const int tx = tid & 31, ty = tid >> 5;       // 32 x 32
        const int i = i0 + tx;
        if (i < NIN) tile[ty][tx] = W[(o0 + ty) * NIN + i];
        __syncthreads();
        const int i2 = i0 + ty;
        if (i2 < NIN) g_wt[i2 * NOUT + o0 + tx] = tile[tx][ty];
        return;
    }

    // ----- sort + pack path -----
    const int b = bid;
    const int lane = tid & 31, wid = tid >> 5;

    cnt[tid] = 0; cnt[tid + 1024] = 0;
    __syncthreads();

    for (int i = tid; i < NIN; i += 1024) {
        const float t = get_t(x, pulse, b, i);
        atomicAdd(&cnt[bucket_of(t)], 1);
    }
    __syncthreads();

    {
        const int v0 = cnt[2 * tid], v1 = cnt[2 * tid + 1];
        float s = (float)(v0 + v1);
        #pragma unroll
        for (int off = 1; off < 32; off <<= 1) {
            const float u = __shfl_up_sync(0xffffffffu, s, off);
            if (lane >= off) s += u;
        }
        if (lane == 31) wsum[wid] = s;
        __syncthreads();
        if (wid == 0) {
            float ws = wsum[lane];
            #pragma unroll
            for (int off = 1; off < 32; off <<= 1) {
                const float u = __shfl_up_sync(0xffffffffu, ws, off);
                if (lane >= off) ws += u;
            }
            wsum[lane] = ws;
        }
        __syncthreads();
        const int incl = (int)s + (wid ? (int)wsum[wid - 1] : 0);
        const int excl = incl - v0 - v1;
        base[2 * tid]     = excl;
        base[2 * tid + 1] = excl + v0;
        __syncthreads();
        cnt[2 * tid]     = excl;
        cnt[2 * tid + 1] = excl + v0;
    }
    __syncthreads();

    for (int i = tid; i < NIN; i += 1024) {
        const float t = get_t(x, pulse, b, i);
        const int pos = atomicAdd(&cnt[bucket_of(t)], 1);
        keys[pos] = ((unsigned long long)__float_as_uint(t) << 32) | (unsigned)i;
    }
    __syncthreads();

    for (int bk = tid; bk < NBUCK; bk += 1024) {
        const int s0 = base[bk];
        const int s1 = (bk + 1 < NBUCK) ? base[bk + 1] : NIN;
        for (int i = s0 + 1; i < s1; ++i) {
            const unsigned long long v = keys[i];
            int j = i - 1;
            while (j >= s0 && keys[j] > v) { keys[j + 1] = keys[j]; --j; }
            keys[j + 1] = v;
        }
    }
    __syncthreads();

    for (int i = tid; i < STRIDE; i += 1024) {
        if (i < NIN) {
            const unsigned long long v = keys[i];
            const float t = __uint_as_float((unsigned)(v >> 32));
            const int idx = (int)(unsigned)v;
            const float z = expf(t);
            g_pack[b * STRIDE + i] = make_float4(t, z, z * t, __int_as_float(idx));
        } else {
            g_pack[b * STRIDE + i] = make_float4(KNS, 0.0f, 0.0f, 0.0f);
        }
    }
}

// ---------------------------------------------------------------------------
// Kernel 2: one THREAD per (batch, output). Serial causal-set scan, groups
// of 8 with branchless validity mask; coalesced transposed-weight reads;
// ONE branch + select per group; one Lambert solve at the end.
// ---------------------------------------------------------------------------
__global__ void __launch_bounds__(32)
solve_kernel(float* __restrict__ out) {
    const int gt = blockIdx.x * 32 + threadIdx.x;
    const int b  = gt >> 9;
    const int o  = gt & 511;

    const float4* __restrict__ pk = g_pack + b * STRIDE;
    const float*  __restrict__ wt = g_wt;

    float A = 0.0f, Bv = 0.0f;
    float fA = 1.0f, fB = 0.0f;
    bool  found = false;

    for (int k0 = 0; k0 < NIN; k0 += GROUP) {
        // batched loads: 8 pk entries (warp-broadcast) + lookahead head
        float4 p[GROUP];
        #pragma unroll
        for (int j = 0; j < GROUP; ++j) p[j] = pk[k0 + j];
        const float4 q = pk[k0 + GROUP];

        // coalesced weight reads: Wt[idx*512 + o] — 1 line per j per warp
        float w[GROUP];
        #pragma unroll
        for (int j = 0; j < GROUP; ++j)
            w[j] = wt[__float_as_int(p[j].w) * NOUT + o];

        // accumulate + branchless validity bits
        float Aj[GROUP], Bj[GROUP];
        unsigned m = 0;
        #pragma unroll
        for (int j = 0; j < GROUP; ++j) {
            A  = fmaf(w[j], p[j].y, A);
            Bv = fmaf(w[j], p[j].z, Bv);
            Aj[j] = A; Bj[j] = Bv;
            const float tn = (j < GROUP - 1) ? p[j + 1].x : q.x;
            const float zn = (j < GROUP - 1) ? p[j + 1].y : q.y;
            const float lnA = __logf(A);      // NaN/-inf if A<=0 -> tests false
            const bool valid =
                   (A > 1e-10f)
                && (fmaf(A, lnA - 1.0f, -Bv) >= 0.0f)     // reach: arg >= -1/e
                && (fmaf(A, p[j].x, -Bv) <= p[j].y)       // t* >= t_k
                && ((tn >= lnA) || (fmaf(A, tn, -Bv) >= zn)) // t* <= t_{k+1}
                && (p[j].x < KNS);
            m |= (valid ? 1u : 0u) << j;
        }

        if (m && !found) {
            const int jw = __ffs((int)m) - 1;
            #pragma unroll
            for (int j = 0; j < GROUP; ++j)
                if (j == jw) { fA = Aj[j]; fB = Bj[j]; }
            found = true;
        }
        if (__all_sync(0xffffffffu, found)) break;
    }

    // one Lambert solve per thread
    float tc = KNS;
    if (found) {
        const float boa = fB / fA;
        float xw = -1.0f / fA * expf(fminf(boa, 80.0f));
        xw = fmaxf(fminf(xw, 0.0f), MINW);
        float wv;
        if (xw < -0.25f) {
            const float pbr = sqrtf(fmaxf(2.0f * (1.0f + EF * xw), 0.0f));
            wv = -1.0f + pbr * (1.0f + pbr * (-0.33333333f + pbr * 0.15277778f));
        } else {
            wv = xw * (1.0f - xw * (1.0f - 1.5f * xw));
        }
        #pragma unroll
        for (int it = 0; it < 3; ++it) {
            const float ew = expf(wv);
            const float f  = wv * ew - xw;
            const float denom = ew * (wv + 1.0f)
                      - (wv + 2.0f) * f / (2.0f * (wv + 1.0f) + 1e-12f);
            wv = wv - f / (denom + 1e-12f);
        }
        tc = boa - wv;
    }
    out[b * NOUT + o] = tc;
}

// ---------------------------------------------------------------------------
extern "C" void kernel_launch(void* const* d_in, const int* in_sizes, int n_in,
                              void* d_out, int out_size) {
    const float* x      = (const float*)d_in[0];   // [32, 1024]
    const float* weight = (const float*)d_in[1];   // [512, 1034]
    const float* pulse  = (const float*)d_in[2];   // [10]
    float* out = (float*)d_out;                    // [32, 512]

    // fused: 32 sort blocks + 528 transpose tiles
    prep_kernel<<<NB + ITILES * OTILES, 1024>>>(x, pulse, weight);

    // one thread per (b,o): 16384 threads, 32-thr blocks for max SM spread
    solve_kernel<<<(NB * NOUT) / 32, 32>>>(out);
}